// round 4
// baseline (speedup 1.0000x reference)
#include <cuda_runtime.h>
#include <cuda_bf16.h>

#define NUM_GRAPHS 2048
#define D 128
#define EPS 1e-6f

// segment start offsets (start[b] = first row of segment b, start[B] = N)
__device__ int g_seg_start[NUM_GRAPHS + 1];
// fused per-(segment, column) tables, float4-packed over columns (32 groups of 4)
__device__ float4 g_mm[NUM_GRAPHS * 32];   // mean * mean_scale
__device__ float4 g_wd[NUM_GRAPHS * 32];   // weight * rstd
// 1 if segment_ids is int64 (little-endian: odd words are zero high-words)
__device__ int g_ids_is64;

static __device__ __forceinline__ int clamp_seg(int g) {
    return g < 0 ? 0 : (g >= NUM_GRAPHS ? NUM_GRAPHS - 1 : g);
}

// ---------------- dtype probe (in-bounds for both dtypes) ----------------
__global__ void detect_kernel(const int* __restrict__ ids32, int n) {
    // int32: word n-1 = last id (~2047, nonzero). int64: word n-1 is a high word = 0.
    g_ids_is64 = (n > 1 && ids32[n - 1] == 0) ? 1 : 0;
}

// ---------------- boundaries from sorted ids ----------------
__global__ void seg_bounds_kernel(const int* __restrict__ ids32, int n) {
    const int mul = g_ids_is64 ? 2 : 1;   // low word of each id
    int i = blockIdx.x * blockDim.x + threadIdx.x;
    if (i >= n) return;
    int g    = clamp_seg(ids32[(long long)i * mul]);
    int prev = (i == 0) ? -1 : clamp_seg(ids32[(long long)(i - 1) * mul]);
    for (int j = prev + 1; j <= g; ++j) g_seg_start[j] = i;
    if (i == n - 1) {
        for (int j = g + 1; j <= NUM_GRAPHS; ++j) g_seg_start[j] = n;
    }
}

// ---------------- kernel 1: per-segment moments -> tables ----------------
// One block per segment. 256 threads = 8 warps; lane (t%32) owns 4 columns
// via float4; warp w processes rows s+w, s+w+8, ...
__global__ void __launch_bounds__(256) stats_kernel(
    const float* __restrict__ feat,
    const float* __restrict__ weight,
    const float* __restrict__ mean_scale)
{
    __shared__ float4 s_sum[8][32];
    __shared__ float4 s_sq[8][32];

    const int seg  = blockIdx.x;
    const int s    = g_seg_start[seg];
    const int e    = g_seg_start[seg + 1];
    const int cnt  = e - s;
    const int lane = threadIdx.x & 31;   // column group (4 cols)
    const int wrp  = threadIdx.x >> 5;   // 0..7

    float4 sum = make_float4(0.f, 0.f, 0.f, 0.f);
    float4 sq  = make_float4(0.f, 0.f, 0.f, 0.f);

    const float4* p = (const float4*)(feat) + (long long)s * 32 + lane;
    int r = wrp;
    // unroll-4 over row stride 8 for MLP
    for (; r + 24 < cnt; r += 32) {
        float4 x0 = p[(long long)(r +  0) * 32];
        float4 x1 = p[(long long)(r +  8) * 32];
        float4 x2 = p[(long long)(r + 16) * 32];
        float4 x3 = p[(long long)(r + 24) * 32];
        sum.x += x0.x + x1.x + x2.x + x3.x;  sum.y += x0.y + x1.y + x2.y + x3.y;
        sum.z += x0.z + x1.z + x2.z + x3.z;  sum.w += x0.w + x1.w + x2.w + x3.w;
        sq.x += x0.x*x0.x + x1.x*x1.x + x2.x*x2.x + x3.x*x3.x;
        sq.y += x0.y*x0.y + x1.y*x1.y + x2.y*x2.y + x3.y*x3.y;
        sq.z += x0.z*x0.z + x1.z*x1.z + x2.z*x2.z + x3.z*x3.z;
        sq.w += x0.w*x0.w + x1.w*x1.w + x2.w*x2.w + x3.w*x3.w;
    }
    for (; r < cnt; r += 8) {
        float4 x = p[(long long)r * 32];
        sum.x += x.x; sum.y += x.y; sum.z += x.z; sum.w += x.w;
        sq.x += x.x*x.x; sq.y += x.y*x.y; sq.z += x.z*x.z; sq.w += x.w*x.w;
    }

    s_sum[wrp][lane] = sum;
    s_sq[wrp][lane]  = sq;
    __syncthreads();

    if (threadIdx.x < 32) {
        float4 ts = s_sum[0][lane], tq = s_sq[0][lane];
        #pragma unroll
        for (int w = 1; w < 8; ++w) {
            float4 a = s_sum[w][lane], b = s_sq[w][lane];
            ts.x += a.x; ts.y += a.y; ts.z += a.z; ts.w += a.w;
            tq.x += b.x; tq.y += b.y; tq.z += b.z; tq.w += b.w;
        }
        const float inv = 1.f / (float)max(cnt, 1);
        float4 msv = ((const float4*)mean_scale)[lane];
        float4 wv  = ((const float4*)weight)[lane];
        float4 mm, wd;

        float mean, v;
        mean = ts.x * inv; mm.x = mean * msv.x;
        v = tq.x * inv - 2.f * mm.x * mean + mm.x * mm.x; wd.x = wv.x * rsqrtf(v + EPS);
        mean = ts.y * inv; mm.y = mean * msv.y;
        v = tq.y * inv - 2.f * mm.y * mean + mm.y * mm.y; wd.y = wv.y * rsqrtf(v + EPS);
        mean = ts.z * inv; mm.z = mean * msv.z;
        v = tq.z * inv - 2.f * mm.z * mean + mm.z * mm.z; wd.z = wv.z * rsqrtf(v + EPS);
        mean = ts.w * inv; mm.w = mean * msv.w;
        v = tq.w * inv - 2.f * mm.w * mean + mm.w * mm.w; wd.w = wv.w * rsqrtf(v + EPS);

        g_mm[seg * 32 + lane] = mm;
        g_wd[seg * 32 + lane] = wd;
    }
}

// ---------------- kernel 2: normalize + write ----------------
// Grid-stride over all N*32 float4 elements. 8 consecutive threads share a row.
__global__ void __launch_bounds__(256) apply_kernel(
    const float* __restrict__ feat,
    const int* __restrict__ ids32,
    const float* __restrict__ bias,
    float* __restrict__ out,
    int n)
{
    const int mul = g_ids_is64 ? 2 : 1;
    const long long total  = (long long)n * 32;
    const long long stride = (long long)gridDim.x * blockDim.x;
    long long i = (long long)blockIdx.x * blockDim.x + threadIdx.x;
    const float4* fp = (const float4*)feat;
    float4*       op = (float4*)out;

    for (; i + 3 * stride < total; i += 4 * stride) {
        long long i0 = i, i1 = i + stride, i2 = i + 2 * stride, i3 = i + 3 * stride;
        float4 x0 = fp[i0], x1 = fp[i1], x2 = fp[i2], x3 = fp[i3];
        int s0 = clamp_seg(ids32[(i0 >> 5) * mul]), s1 = clamp_seg(ids32[(i1 >> 5) * mul]);
        int s2 = clamp_seg(ids32[(i2 >> 5) * mul]), s3 = clamp_seg(ids32[(i3 >> 5) * mul]);
        int c0 = (int)(i0 & 31), c1 = (int)(i1 & 31), c2 = (int)(i2 & 31), c3 = (int)(i3 & 31);
        float4 m0 = g_mm[s0 * 32 + c0], w0 = g_wd[s0 * 32 + c0];
        float4 m1 = g_mm[s1 * 32 + c1], w1 = g_wd[s1 * 32 + c1];
        float4 m2 = g_mm[s2 * 32 + c2], w2 = g_wd[s2 * 32 + c2];
        float4 m3 = g_mm[s3 * 32 + c3], w3 = g_wd[s3 * 32 + c3];
        float4 b0 = ((const float4*)bias)[c0], b1 = ((const float4*)bias)[c1];
        float4 b2 = ((const float4*)bias)[c2], b3 = ((const float4*)bias)[c3];
        float4 r0, r1, r2, r3;
        r0.x = fmaf(w0.x, x0.x - m0.x, b0.x); r0.y = fmaf(w0.y, x0.y - m0.y, b0.y);
        r0.z = fmaf(w0.z, x0.z - m0.z, b0.z); r0.w = fmaf(w0.w, x0.w - m0.w, b0.w);
        r1.x = fmaf(w1.x, x1.x - m1.x, b1.x); r1.y = fmaf(w1.y, x1.y - m1.y, b1.y);
        r1.z = fmaf(w1.z, x1.z - m1.z, b1.z); r1.w = fmaf(w1.w, x1.w - m1.w, b1.w);
        r2.x = fmaf(w2.x, x2.x - m2.x, b2.x); r2.y = fmaf(w2.y, x2.y - m2.y, b2.y);
        r2.z = fmaf(w2.z, x2.z - m2.z, b2.z); r2.w = fmaf(w2.w, x2.w - m2.w, b2.w);
        r3.x = fmaf(w3.x, x3.x - m3.x, b3.x); r3.y = fmaf(w3.y, x3.y - m3.y, b3.y);
        r3.z = fmaf(w3.z, x3.z - m3.z, b3.z); r3.w = fmaf(w3.w, x3.w - m3.w, b3.w);
        op[i0] = r0; op[i1] = r1; op[i2] = r2; op[i3] = r3;
    }
    for (; i < total; i += stride) {
        float4 x = fp[i];
        int s = clamp_seg(ids32[(i >> 5) * mul]);
        int c = (int)(i & 31);
        float4 m = g_mm[s * 32 + c], w = g_wd[s * 32 + c];
        float4 b = ((const float4*)bias)[c];
        float4 r;
        r.x = fmaf(w.x, x.x - m.x, b.x); r.y = fmaf(w.y, x.y - m.y, b.y);
        r.z = fmaf(w.z, x.z - m.z, b.z); r.w = fmaf(w.w, x.w - m.w, b.w);
        op[i] = r;
    }
}

extern "C" void kernel_launch(void* const* d_in, const int* in_sizes, int n_in,
                              void* d_out, int out_size) {
    const float* feat = (const float*)d_in[0];
    const int*   ids  = (const int*)d_in[1];   // int32 expected; int64 auto-detected
    const float* w    = (const float*)d_in[2];
    const float* b    = (const float*)d_in[3];
    const float* ms   = (const float*)d_in[4];
    float* out = (float*)d_out;
    const int n = in_sizes[1];  // number of nodes

    detect_kernel<<<1, 1>>>(ids, n);
    seg_bounds_kernel<<<(n + 255) / 256, 256>>>(ids, n);
    stats_kernel<<<NUM_GRAPHS, 256>>>(feat, w, ms);
    apply_kernel<<<148 * 16, 256>>>(feat, ids, b, out, n);
}

// round 13
// speedup vs baseline: 1.4236x; 1.4236x over previous
#include <cuda_runtime.h>
#include <cuda_bf16.h>

#define NUM_GRAPHS 2048
#define D 128
#define EPS 1e-6f
#define NW 16          // warps per block
#define NT (NW * 32)   // 512 threads

// segment start offsets (start[b] = first row of segment b, start[B] = N)
__device__ int g_seg_start[NUM_GRAPHS + 1];
// 1 if segment_ids is int64 (little-endian: odd words are zero high-words)
__device__ int g_ids_is64;

static __device__ __forceinline__ int clamp_seg(int g) {
    return g < 0 ? 0 : (g >= NUM_GRAPHS ? NUM_GRAPHS - 1 : g);
}

// 256-bit first-touch load with evict_last (the exact form ptxas requires:
// ".L2::evict_last" is only legal with .v8.b32 / .v4.b64)
static __device__ __forceinline__ void ldg_keep8(const float* p, float4& lo, float4& hi) {
    unsigned a0, a1, a2, a3, a4, a5, a6, a7;
    asm volatile("ld.global.nc.L2::evict_last.v8.b32 {%0,%1,%2,%3,%4,%5,%6,%7}, [%8];"
                 : "=r"(a0), "=r"(a1), "=r"(a2), "=r"(a3),
                   "=r"(a4), "=r"(a5), "=r"(a6), "=r"(a7)
                 : "l"(p));
    lo.x = __uint_as_float(a0); lo.y = __uint_as_float(a1);
    lo.z = __uint_as_float(a2); lo.w = __uint_as_float(a3);
    hi.x = __uint_as_float(a4); hi.y = __uint_as_float(a5);
    hi.z = __uint_as_float(a6); hi.w = __uint_as_float(a7);
}

static __device__ __forceinline__ void acc8(const float4& lo, const float4& hi,
                                            float4& slo, float4& shi,
                                            float4& qlo, float4& qhi) {
    slo.x += lo.x; slo.y += lo.y; slo.z += lo.z; slo.w += lo.w;
    shi.x += hi.x; shi.y += hi.y; shi.z += hi.z; shi.w += hi.w;
    qlo.x += lo.x * lo.x; qlo.y += lo.y * lo.y; qlo.z += lo.z * lo.z; qlo.w += lo.w * lo.w;
    qhi.x += hi.x * hi.x; qhi.y += hi.y * hi.y; qhi.z += hi.z * hi.z; qhi.w += hi.w * hi.w;
}

// ---------------- dtype probe (in-bounds for both dtypes) ----------------
__global__ void detect_kernel(const int* __restrict__ ids32, int n) {
    g_ids_is64 = (n > 1 && ids32[n - 1] == 0) ? 1 : 0;
}

// ---------------- boundaries from sorted ids ----------------
__global__ void seg_bounds_kernel(const int* __restrict__ ids32, int n) {
    const int mul = g_ids_is64 ? 2 : 1;   // low word of each id
    int i = blockIdx.x * blockDim.x + threadIdx.x;
    if (i >= n) return;
    int g    = clamp_seg(ids32[(long long)i * mul]);
    int prev = (i == 0) ? -1 : clamp_seg(ids32[(long long)(i - 1) * mul]);
    for (int j = prev + 1; j <= g; ++j) g_seg_start[j] = i;
    if (i == n - 1) {
        for (int j = g + 1; j <= NUM_GRAPHS; ++j) g_seg_start[j] = n;
    }
}

// ---------------- fused kernel: per-segment moments + normalize ----------------
// One block per segment, 512 threads. Thread owns 8 contiguous columns
// (lane8 = tid&15); "part" = tid>>4 in [0,32) selects its row stream
// (rows part, part+32, ...). A warp's two halves cover two adjacent rows =
// 1024 contiguous bytes. Pass A: 256-bit evict_last loads; pass B: streaming
// __ldcs/__stcs with stats broadcast through smem.
__global__ void __launch_bounds__(NT, 2) graphnorm_fused_kernel(
    const float* __restrict__ feat,
    const float* __restrict__ weight,
    const float* __restrict__ bias,
    const float* __restrict__ mean_scale,
    float* __restrict__ out)
{
    __shared__ float4 s_lo[32][16];   // per-part partial sums, low 4 cols
    __shared__ float4 s_hi[32][16];   // high 4 cols
    __shared__ float4 q_lo[32][16];   // partial sumsq
    __shared__ float4 q_hi[32][16];
    __shared__ float4 s_mm[32];       // [lane8] = lo, [lane8+16] = hi
    __shared__ float4 s_wd[32];

    const int seg   = blockIdx.x;
    const int s     = g_seg_start[seg];
    const int e     = g_seg_start[seg + 1];
    const int cnt   = e - s;
    const int lane8 = threadIdx.x & 15;   // column group (8 cols)
    const int part  = threadIdx.x >> 4;   // 0..31: row stream

    if (cnt <= 0) return;   // block-uniform: barrier-safe

    const float* base = feat + (long long)s * D + lane8 * 8;

    float4 slo = make_float4(0.f, 0.f, 0.f, 0.f), shi = slo, qlo = slo, qhi = slo;

    // ---- pass A: moments (unroll-2, row stride 32) ----
    int r = part;
    for (; r + 32 < cnt; r += 64) {
        float4 l0, h0, l1, h1;
        ldg_keep8(base + (long long)r * D, l0, h0);
        ldg_keep8(base + (long long)(r + 32) * D, l1, h1);
        acc8(l0, h0, slo, shi, qlo, qhi);
        acc8(l1, h1, slo, shi, qlo, qhi);
    }
    if (r < cnt) {
        float4 l0, h0;
        ldg_keep8(base + (long long)r * D, l0, h0);
        acc8(l0, h0, slo, shi, qlo, qhi);
    }

    s_lo[part][lane8] = slo;  s_hi[part][lane8] = shi;
    q_lo[part][lane8] = qlo;  q_hi[part][lane8] = qhi;
    __syncthreads();

    // ---- reduce + finalize (threads 0-15: lo halves, 16-31: hi halves) ----
    if (threadIdx.x < 32) {
        const int  l  = threadIdx.x & 15;
        const bool hi = threadIdx.x >= 16;
        float4 ts = make_float4(0.f, 0.f, 0.f, 0.f), tq = ts;
        #pragma unroll
        for (int w = 0; w < 32; ++w) {
            float4 a = hi ? s_hi[w][l] : s_lo[w][l];
            float4 b = hi ? q_hi[w][l] : q_lo[w][l];
            ts.x += a.x; ts.y += a.y; ts.z += a.z; ts.w += a.w;
            tq.x += b.x; tq.y += b.y; tq.z += b.z; tq.w += b.w;
        }
        const float inv = 1.f / (float)cnt;
        float4 msv = ((const float4*)mean_scale)[l * 2 + (hi ? 1 : 0)];
        float4 wv  = ((const float4*)weight)[l * 2 + (hi ? 1 : 0)];
        float4 mm, wd;
        float mean, v;
        mean = ts.x * inv; mm.x = mean * msv.x;
        v = tq.x * inv - 2.f * mm.x * mean + mm.x * mm.x; wd.x = wv.x * rsqrtf(v + EPS);
        mean = ts.y * inv; mm.y = mean * msv.y;
        v = tq.y * inv - 2.f * mm.y * mean + mm.y * mm.y; wd.y = wv.y * rsqrtf(v + EPS);
        mean = ts.z * inv; mm.z = mean * msv.z;
        v = tq.z * inv - 2.f * mm.z * mean + mm.z * mm.z; wd.z = wv.z * rsqrtf(v + EPS);
        mean = ts.w * inv; mm.w = mean * msv.w;
        v = tq.w * inv - 2.f * mm.w * mean + mm.w * mm.w; wd.w = wv.w * rsqrtf(v + EPS);
        s_mm[threadIdx.x] = mm;
        s_wd[threadIdx.x] = wd;
    }
    __syncthreads();

    const float4 mmlo = s_mm[lane8],      mmhi = s_mm[lane8 + 16];
    const float4 wdlo = s_wd[lane8],      wdhi = s_wd[lane8 + 16];
    const float4 bvlo = ((const float4*)bias)[lane8 * 2];
    const float4 bvhi = ((const float4*)bias)[lane8 * 2 + 1];

    // ---- pass B: normalize + write (unroll-2, streaming) ----
    const float4* pf = (const float4*)(feat) + (long long)s * 32 + lane8 * 2;
    float4*       po = (float4*)(out)        + (long long)s * 32 + lane8 * 2;
    r = part;
    for (; r + 32 < cnt; r += 64) {
        float4 x0 = __ldcs(pf + (long long)r * 32);
        float4 y0 = __ldcs(pf + (long long)r * 32 + 1);
        float4 x1 = __ldcs(pf + (long long)(r + 32) * 32);
        float4 y1 = __ldcs(pf + (long long)(r + 32) * 32 + 1);
        float4 a, b;
        a.x = fmaf(wdlo.x, x0.x - mmlo.x, bvlo.x); a.y = fmaf(wdlo.y, x0.y - mmlo.y, bvlo.y);
        a.z = fmaf(wdlo.z, x0.z - mmlo.z, bvlo.z); a.w = fmaf(wdlo.w, x0.w - mmlo.w, bvlo.w);
        b.x = fmaf(wdhi.x, y0.x - mmhi.x, bvhi.x); b.y = fmaf(wdhi.y, y0.y - mmhi.y, bvhi.y);
        b.z = fmaf(wdhi.z, y0.z - mmhi.z, bvhi.z); b.w = fmaf(wdhi.w, y0.w - mmhi.w, bvhi.w);
        __stcs(po + (long long)r * 32, a);
        __stcs(po + (long long)r * 32 + 1, b);
        a.x = fmaf(wdlo.x, x1.x - mmlo.x, bvlo.x); a.y = fmaf(wdlo.y, x1.y - mmlo.y, bvlo.y);
        a.z = fmaf(wdlo.z, x1.z - mmlo.z, bvlo.z); a.w = fmaf(wdlo.w, x1.w - mmlo.w, bvlo.w);
        b.x = fmaf(wdhi.x, y1.x - mmhi.x, bvhi.x); b.y = fmaf(wdhi.y, y1.y - mmhi.y, bvhi.y);
        b.z = fmaf(wdhi.z, y1.z - mmhi.z, bvhi.z); b.w = fmaf(wdhi.w, y1.w - mmhi.w, bvhi.w);
        __stcs(po + (long long)(r + 32) * 32, a);
        __stcs(po + (long long)(r + 32) * 32 + 1, b);
    }
    if (r < cnt) {
        float4 x0 = __ldcs(pf + (long long)r * 32);
        float4 y0 = __ldcs(pf + (long long)r * 32 + 1);
        float4 a, b;
        a.x = fmaf(wdlo.x, x0.x - mmlo.x, bvlo.x); a.y = fmaf(wdlo.y, x0.y - mmlo.y, bvlo.y);
        a.z = fmaf(wdlo.z, x0.z - mmlo.z, bvlo.z); a.w = fmaf(wdlo.w, x0.w - mmlo.w, bvlo.w);
        b.x = fmaf(wdhi.x, y0.x - mmhi.x, bvhi.x); b.y = fmaf(wdhi.y, y0.y - mmhi.y, bvhi.y);
        b.z = fmaf(wdhi.z, y0.z - mmhi.z, bvhi.z); b.w = fmaf(wdhi.w, y0.w - mmhi.w, bvhi.w);
        __stcs(po + (long long)r * 32, a);
        __stcs(po + (long long)r * 32 + 1, b);
    }
}

extern "C" void kernel_launch(void* const* d_in, const int* in_sizes, int n_in,
                              void* d_out, int out_size) {
    const float* feat = (const float*)d_in[0];
    const int*   ids  = (const int*)d_in[1];   // int32 expected; int64 auto-detected
    const float* w    = (const float*)d_in[2];
    const float* b    = (const float*)d_in[3];
    const float* ms   = (const float*)d_in[4];
    float* out = (float*)d_out;
    const int n = in_sizes[1];  // number of nodes

    detect_kernel<<<1, 1>>>(ids, n);
    seg_bounds_kernel<<<(n + 255) / 256, 256>>>(ids, n);
    graphnorm_fused_kernel<<<NUM_GRAPHS, NT>>>(feat, w, b, ms, out);
}

// round 15
// speedup vs baseline: 1.4242x; 1.0005x over previous
#include <cuda_runtime.h>
#include <cuda_bf16.h>

#define NUM_GRAPHS 2048
#define D 128
#define EPS 1e-6f
#define NW 16          // warps per block
#define NT (NW * 32)   // 512 threads

// segment start offsets (start[b] = first row of segment b, start[B] = N)
__device__ int g_seg_start[NUM_GRAPHS + 1];

static __device__ __forceinline__ int clamp_seg(int g) {
    return g < 0 ? 0 : (g >= NUM_GRAPHS ? NUM_GRAPHS - 1 : g);
}

// 256-bit first-touch load with evict_last (the exact form ptxas requires:
// ".L2::evict_last" is only legal with .v8.b32 / .v4.b64)
static __device__ __forceinline__ void ldg_keep8(const float* p, float4& lo, float4& hi) {
    unsigned a0, a1, a2, a3, a4, a5, a6, a7;
    asm volatile("ld.global.nc.L2::evict_last.v8.b32 {%0,%1,%2,%3,%4,%5,%6,%7}, [%8];"
                 : "=r"(a0), "=r"(a1), "=r"(a2), "=r"(a3),
                   "=r"(a4), "=r"(a5), "=r"(a6), "=r"(a7)
                 : "l"(p));
    lo.x = __uint_as_float(a0); lo.y = __uint_as_float(a1);
    lo.z = __uint_as_float(a2); lo.w = __uint_as_float(a3);
    hi.x = __uint_as_float(a4); hi.y = __uint_as_float(a5);
    hi.z = __uint_as_float(a6); hi.w = __uint_as_float(a7);
}

static __device__ __forceinline__ void acc8(const float4& lo, const float4& hi,
                                            float4& slo, float4& shi,
                                            float4& qlo, float4& qhi) {
    slo.x += lo.x; slo.y += lo.y; slo.z += lo.z; slo.w += lo.w;
    shi.x += hi.x; shi.y += hi.y; shi.z += hi.z; shi.w += hi.w;
    qlo.x += lo.x * lo.x; qlo.y += lo.y * lo.y; qlo.z += lo.z * lo.z; qlo.w += lo.w * lo.w;
    qhi.x += hi.x * hi.x; qhi.y += hi.y * hi.y; qhi.z += hi.z * hi.z; qhi.w += hi.w * hi.w;
}

// ---------------- boundaries from sorted ids (dtype probe inlined) ----------------
__global__ void seg_bounds_kernel(const int* __restrict__ ids32, int n) {
    // int32: word n-1 = last id (~2047, nonzero). int64 LE: word n-1 is a high word = 0.
    // Same address for all threads -> one broadcast L2 access.
    const int mul = (n > 1 && ids32[n - 1] == 0) ? 2 : 1;
    int i = blockIdx.x * blockDim.x + threadIdx.x;
    if (i >= n) return;
    int g    = clamp_seg(ids32[(long long)i * mul]);
    int prev = (i == 0) ? -1 : clamp_seg(ids32[(long long)(i - 1) * mul]);
    for (int j = prev + 1; j <= g; ++j) g_seg_start[j] = i;
    if (i == n - 1) {
        for (int j = g + 1; j <= NUM_GRAPHS; ++j) g_seg_start[j] = n;
    }
}

// ---------------- fused kernel: per-segment moments + normalize ----------------
// One block per segment, 512 threads. Thread owns 8 contiguous columns
// (lane8 = tid&15); "part" = tid>>4 in [0,32) selects its row stream
// (rows part, part+32, ...). A warp's two halves cover two adjacent rows =
// 1024 contiguous bytes. Pass A: 256-bit evict_last loads; pass B: streaming
// __ldcs/__stcs with stats broadcast through smem.
__global__ void __launch_bounds__(NT, 2) graphnorm_fused_kernel(
    const float* __restrict__ feat,
    const float* __restrict__ weight,
    const float* __restrict__ bias,
    const float* __restrict__ mean_scale,
    float* __restrict__ out)
{
    __shared__ float4 s_lo[32][16];   // per-part partial sums, low 4 cols
    __shared__ float4 s_hi[32][16];   // high 4 cols
    __shared__ float4 q_lo[32][16];   // partial sumsq
    __shared__ float4 q_hi[32][16];
    __shared__ float4 s_mm[32];       // [lane8] = lo, [lane8+16] = hi
    __shared__ float4 s_wd[32];

    const int seg   = blockIdx.x;
    const int s     = g_seg_start[seg];
    const int e     = g_seg_start[seg + 1];
    const int cnt   = e - s;
    const int lane8 = threadIdx.x & 15;   // column group (8 cols)
    const int part  = threadIdx.x >> 4;   // 0..31: row stream

    if (cnt <= 0) return;   // block-uniform: barrier-safe

    const float* base = feat + (long long)s * D + lane8 * 8;

    float4 slo = make_float4(0.f, 0.f, 0.f, 0.f), shi = slo, qlo = slo, qhi = slo;

    // ---- pass A: moments (unroll-2, row stride 32) ----
    int r = part;
    for (; r + 32 < cnt; r += 64) {
        float4 l0, h0, l1, h1;
        ldg_keep8(base + (long long)r * D, l0, h0);
        ldg_keep8(base + (long long)(r + 32) * D, l1, h1);
        acc8(l0, h0, slo, shi, qlo, qhi);
        acc8(l1, h1, slo, shi, qlo, qhi);
    }
    if (r < cnt) {
        float4 l0, h0;
        ldg_keep8(base + (long long)r * D, l0, h0);
        acc8(l0, h0, slo, shi, qlo, qhi);
    }

    s_lo[part][lane8] = slo;  s_hi[part][lane8] = shi;
    q_lo[part][lane8] = qlo;  q_hi[part][lane8] = qhi;
    __syncthreads();

    // ---- reduce + finalize (threads 0-15: lo halves, 16-31: hi halves) ----
    if (threadIdx.x < 32) {
        const int  l  = threadIdx.x & 15;
        const bool hi = threadIdx.x >= 16;
        float4 ts = make_float4(0.f, 0.f, 0.f, 0.f), tq = ts;
        #pragma unroll
        for (int w = 0; w < 32; ++w) {
            float4 a = hi ? s_hi[w][l] : s_lo[w][l];
            float4 b = hi ? q_hi[w][l] : q_lo[w][l];
            ts.x += a.x; ts.y += a.y; ts.z += a.z; ts.w += a.w;
            tq.x += b.x; tq.y += b.y; tq.z += b.z; tq.w += b.w;
        }
        const float inv = 1.f / (float)cnt;
        float4 msv = ((const float4*)mean_scale)[l * 2 + (hi ? 1 : 0)];
        float4 wv  = ((const float4*)weight)[l * 2 + (hi ? 1 : 0)];
        float4 mm, wd;
        float mean, v;
        mean = ts.x * inv; mm.x = mean * msv.x;
        v = tq.x * inv - 2.f * mm.x * mean + mm.x * mm.x; wd.x = wv.x * rsqrtf(v + EPS);
        mean = ts.y * inv; mm.y = mean * msv.y;
        v = tq.y * inv - 2.f * mm.y * mean + mm.y * mm.y; wd.y = wv.y * rsqrtf(v + EPS);
        mean = ts.z * inv; mm.z = mean * msv.z;
        v = tq.z * inv - 2.f * mm.z * mean + mm.z * mm.z; wd.z = wv.z * rsqrtf(v + EPS);
        mean = ts.w * inv; mm.w = mean * msv.w;
        v = tq.w * inv - 2.f * mm.w * mean + mm.w * mm.w; wd.w = wv.w * rsqrtf(v + EPS);
        s_mm[threadIdx.x] = mm;
        s_wd[threadIdx.x] = wd;
    }
    __syncthreads();

    const float4 mmlo = s_mm[lane8],      mmhi = s_mm[lane8 + 16];
    const float4 wdlo = s_wd[lane8],      wdhi = s_wd[lane8 + 16];
    const float4 bvlo = ((const float4*)bias)[lane8 * 2];
    const float4 bvhi = ((const float4*)bias)[lane8 * 2 + 1];

    // ---- pass B: normalize + write (unroll-2, streaming) ----
    const float4* pf = (const float4*)(feat) + (long long)s * 32 + lane8 * 2;
    float4*       po = (float4*)(out)        + (long long)s * 32 + lane8 * 2;
    r = part;
    for (; r + 32 < cnt; r += 64) {
        float4 x0 = __ldcs(pf + (long long)r * 32);
        float4 y0 = __ldcs(pf + (long long)r * 32 + 1);
        float4 x1 = __ldcs(pf + (long long)(r + 32) * 32);
        float4 y1 = __ldcs(pf + (long long)(r + 32) * 32 + 1);
        float4 a, b;
        a.x = fmaf(wdlo.x, x0.x - mmlo.x, bvlo.x); a.y = fmaf(wdlo.y, x0.y - mmlo.y, bvlo.y);
        a.z = fmaf(wdlo.z, x0.z - mmlo.z, bvlo.z); a.w = fmaf(wdlo.w, x0.w - mmlo.w, bvlo.w);
        b.x = fmaf(wdhi.x, y0.x - mmhi.x, bvhi.x); b.y = fmaf(wdhi.y, y0.y - mmhi.y, bvhi.y);
        b.z = fmaf(wdhi.z, y0.z - mmhi.z, bvhi.z); b.w = fmaf(wdhi.w, y0.w - mmhi.w, bvhi.w);
        __stcs(po + (long long)r * 32, a);
        __stcs(po + (long long)r * 32 + 1, b);
        a.x = fmaf(wdlo.x, x1.x - mmlo.x, bvlo.x); a.y = fmaf(wdlo.y, x1.y - mmlo.y, bvlo.y);
        a.z = fmaf(wdlo.z, x1.z - mmlo.z, bvlo.z); a.w = fmaf(wdlo.w, x1.w - mmlo.w, bvlo.w);
        b.x = fmaf(wdhi.x, y1.x - mmhi.x, bvhi.x); b.y = fmaf(wdhi.y, y1.y - mmhi.y, bvhi.y);
        b.z = fmaf(wdhi.z, y1.z - mmhi.z, bvhi.z); b.w = fmaf(wdhi.w, y1.w - mmhi.w, bvhi.w);
        __stcs(po + (long long)(r + 32) * 32, a);
        __stcs(po + (long long)(r + 32) * 32 + 1, b);
    }
    if (r < cnt) {
        float4 x0 = __ldcs(pf + (long long)r * 32);
        float4 y0 = __ldcs(pf + (long long)r * 32 + 1);
        float4 a, b;
        a.x = fmaf(wdlo.x, x0.x - mmlo.x, bvlo.x); a.y = fmaf(wdlo.y, x0.y - mmlo.y, bvlo.y);
        a.z = fmaf(wdlo.z, x0.z - mmlo.z, bvlo.z); a.w = fmaf(wdlo.w, x0.w - mmlo.w, bvlo.w);
        b.x = fmaf(wdhi.x, y0.x - mmhi.x, bvhi.x); b.y = fmaf(wdhi.y, y0.y - mmhi.y, bvhi.y);
        b.z = fmaf(wdhi.z, y0.z - mmhi.z, bvhi.z); b.w = fmaf(wdhi.w, y0.w - mmhi.w, bvhi.w);
        __stcs(po + (long long)r * 32, a);
        __stcs(po + (long long)r * 32 + 1, b);
    }
}

extern "C" void kernel_launch(void* const* d_in, const int* in_sizes, int n_in,
                              void* d_out, int out_size) {
    const float* feat = (const float*)d_in[0];
    const int*   ids  = (const int*)d_in[1];   // int32 expected; int64 auto-detected
    const float* w    = (const float*)d_in[2];
    const float* b    = (const float*)d_in[3];
    const float* ms   = (const float*)d_in[4];
    float* out = (float*)d_out;
    const int n = in_sizes[1];  // number of nodes

    seg_bounds_kernel<<<(n + 255) / 256, 256>>>(ids, n);
    graphnorm_fused_kernel<<<NUM_GRAPHS, NT>>>(feat, w, b, ms, out);
}